// round 17
// baseline (speedup 1.0000x reference)
#include <cuda_runtime.h>
#include <cstdint>

#define TS 65536

// Scratch (device globals — allocation-free per harness rules)
__device__ float g_xg[(size_t)TS * 1024];   // permuted gate preactivations
__device__ float g_hs[(size_t)TS * 256];    // per-step hidden outputs

__device__ __forceinline__ uint32_t smem_u32(const void* p) {
    uint32_t r;
    asm("{ .reg .u64 t; cvta.to.shared.u64 t, %1; cvt.u32.u64 %0, t; }" : "=r"(r) : "l"(p));
    return r;
}

__device__ __forceinline__ float tanhapx(float x) {
    float y;
    asm("tanh.approx.f32 %0, %1;" : "=f"(y) : "f"(x));
    return y;
}
// accurate sigmoid for the fc epilogue (not on critical path)
__device__ __forceinline__ float fsig(float x) {
    return __fdividef(1.0f, 1.0f + __expf(-x));
}

// ---------------------------------------------------------------------------
// GEMM 1: xg[t][r] = b1[r]+b2[r] + sum_k x[t][k] * W_ih2[r][k]
// stored permuted: g_xg[t*1024 + u*4 + g], r = g*256+u  (gate order i,f,g,o)
// ---------------------------------------------------------------------------
__global__ __launch_bounds__(256) void gemm_xg_kernel(
    const float* __restrict__ X,    // [65536,256]
    const float* __restrict__ W,    // [1024,256]
    const float* __restrict__ b1,
    const float* __restrict__ b2)
{
    __shared__ float Xs[32][65];
    __shared__ float Ws[32][65];
    const int lin = threadIdx.x;
    const int tx = lin & 15, ty = lin >> 4;
    const int bt = blockIdx.x * 64;
    const int br = blockIdx.y * 64;
    float acc[4][4] = {};

    for (int k0 = 0; k0 < 256; k0 += 32) {
        int row = lin >> 3, seg = (lin & 7) << 2;
        float4 v = *(const float4*)&X[(size_t)(bt + row) * 256 + k0 + seg];
        Xs[seg+0][row] = v.x; Xs[seg+1][row] = v.y; Xs[seg+2][row] = v.z; Xs[seg+3][row] = v.w;
        float4 v2 = *(const float4*)&X[(size_t)(bt + row + 32) * 256 + k0 + seg];
        Xs[seg+0][row+32] = v2.x; Xs[seg+1][row+32] = v2.y; Xs[seg+2][row+32] = v2.z; Xs[seg+3][row+32] = v2.w;
        float4 w1 = *(const float4*)&W[(size_t)(br + row) * 256 + k0 + seg];
        Ws[seg+0][row] = w1.x; Ws[seg+1][row] = w1.y; Ws[seg+2][row] = w1.z; Ws[seg+3][row] = w1.w;
        float4 w2 = *(const float4*)&W[(size_t)(br + row + 32) * 256 + k0 + seg];
        Ws[seg+0][row+32] = w2.x; Ws[seg+1][row+32] = w2.y; Ws[seg+2][row+32] = w2.z; Ws[seg+3][row+32] = w2.w;
        __syncthreads();
#pragma unroll
        for (int kk = 0; kk < 32; kk++) {
            float a[4], bb[4];
#pragma unroll
            for (int i = 0; i < 4; i++) a[i] = Xs[kk][ty*4 + i];
#pragma unroll
            for (int j = 0; j < 4; j++) bb[j] = Ws[kk][tx*4 + j];
#pragma unroll
            for (int i = 0; i < 4; i++)
#pragma unroll
                for (int j = 0; j < 4; j++) acc[i][j] = fmaf(a[i], bb[j], acc[i][j]);
        }
        __syncthreads();
    }
#pragma unroll
    for (int j = 0; j < 4; j++) {
        int r = br + tx*4 + j;
        float bias = b1[r] + b2[r];
        int u = r & 255, g = r >> 8;
#pragma unroll
        for (int i = 0; i < 4; i++) {
            int t = bt + ty*4 + i;
            g_xg[(size_t)t * 1024 + u*4 + g] = acc[i][j] + bias;
        }
    }
}

// ---------------------------------------------------------------------------
// Sequential scan: one 8-CTA cluster. W_hh2 register-resident (128 regs/thr).
// tid = ul*8 + part ; unit u = rank*32+ul ; cols [part*32, part*32+32).
// Precomputed conflict-free LDS addresses (both buffers), explicit x2 unroll
// (compile-time buf), pointer-incremented g_hs / xg.
// hv loads are asm VOLATILE: without volatile the compiler CSE'd the
// loop-invariant-address loads across iterations (R16 correctness bug).
// ---------------------------------------------------------------------------
__global__ void __cluster_dims__(8, 1, 1) __launch_bounds__(256, 1)
scan_kernel(const float* __restrict__ Whh,
            const float* __restrict__ h0,
            const float* __restrict__ c0)
{
    __shared__ __align__(16) float hb[2][256];
    __shared__ __align__(8)  unsigned long long mbars[2];

    const int tid  = threadIdx.x;
    const int lane = tid & 31;
    const int part = tid & 7;
    const int ul   = tid >> 3;
    uint32_t rank;
    asm("mov.u32 %0, %%cluster_ctarank;" : "=r"(rank));
    const int u    = (int)rank * 32 + ul;
    const int col0 = part * 32;

    // W rows {g*256+u}, rotated chunk order (slot 2*jj = logical chunk
    // (jj+part)&7), gates 0,1,3 pre-scaled by 0.5 for the tanh-sigmoid.
    unsigned long long w[4][16];
#pragma unroll
    for (int g = 0; g < 4; g++) {
        const float gs = (g == 2) ? 1.0f : 0.5f;
        const float* wrow = Whh + (size_t)(g * 256 + u) * 256 + col0;
#pragma unroll
        for (int jj = 0; jj < 8; jj++) {
            const int q = (jj + part) & 7;
            float4 wv = *(const float4*)(wrow + 4 * q);
            wv.x *= gs; wv.y *= gs; wv.z *= gs; wv.w *= gs;
            w[g][2*jj]     = ((unsigned long long)__float_as_uint(wv.y) << 32) | __float_as_uint(wv.x);
            w[g][2*jj + 1] = ((unsigned long long)__float_as_uint(wv.w) << 32) | __float_as_uint(wv.z);
        }
    }

    const uint32_t hb0 = smem_u32(&hb[0][0]);
    const uint32_t mb0 = smem_u32(&mbars[0]);
    const uint32_t mb_delta = mb0 - hb0;

    // precomputed rotated LDS addresses for both buffers (16 regs)
    uint32_t ha0[8], ha1[8];
#pragma unroll
    for (int jj = 0; jj < 8; jj++) {
        const int q = (jj + part) & 7;
        ha0[jj] = hb0 + (uint32_t)(col0 + 4 * q) * 4u;
        ha1[jj] = ha0[jj] + 1024u;
    }

    if (tid == 0) {
        asm volatile("mbarrier.init.shared.b64 [%0], 1;" :: "r"(mb0) : "memory");
        asm volatile("mbarrier.init.shared.b64 [%0], 1;" :: "r"(mb0 + 8) : "memory");
        // pre-arm both buffers (h_1 -> mbar[1], h_2 -> mbar[0]); 256 * 4B
        asm volatile("mbarrier.arrive.expect_tx.shared.b64 _, [%0], %1;" :: "r"(mb0), "r"(1024u) : "memory");
        asm volatile("mbarrier.arrive.expect_tx.shared.b64 _, [%0], %1;" :: "r"(mb0 + 8), "r"(1024u) : "memory");
    }
    hb[0][tid] = h0[tid];          // every CTA preloads full h0 (256 threads)
    __syncthreads();
    asm volatile("barrier.cluster.arrive.aligned;" ::: "memory");
    asm volatile("barrier.cluster.wait.aligned;"   ::: "memory");

    // leader-only state
    float c = 0.0f;
    uint32_t r_hb[8];
    float4 xg_c = make_float4(0.f,0.f,0.f,0.f), xg_n = xg_c;
    const float* xgp = g_xg + (size_t)2 * 1024 + u * 4;   // points at t+2
    float* hsp = g_hs + u;
    if (part == 0) {
        c = c0[u];
#pragma unroll
        for (int k = 0; k < 8; k++)
            asm("mapa.shared::cluster.u32 %0, %1, %2;" : "=r"(r_hb[k]) : "r"(hb0), "r"(k));
        xg_c = *(const float4*)(g_xg + (size_t)0 * 1024 + u * 4);
        xg_c.x *= 0.5f; xg_c.y *= 0.5f; xg_c.w *= 0.5f;
        xg_n = *(const float4*)(g_xg + (size_t)1 * 1024 + u * 4);
        xg_n.x *= 0.5f; xg_n.y *= 0.5f; xg_n.w *= 0.5f;
    }
    const uint32_t dof0 = (uint32_t)(0 * 256 + u) * 4u;   // dest data offset, buf0
    const uint32_t dof1 = (uint32_t)(1 * 256 + u) * 4u;   // dest data offset, buf1
    const uint32_t mof0 = mb_delta;                        // dest mbar offset, buf0
    const uint32_t mof1 = mb_delta + 8u;

    uint32_t par0 = 0u, par1 = 0u;

#define SCAN_STEP(T, BUFLIT, PARVAR, HA, DO_WAIT)                              \
    do {                                                                       \
        if (DO_WAIT) {                                                         \
            const uint32_t mb_ = mb0 + (BUFLIT) * 8u;                          \
            if (lane == 0) {                                                   \
                uint32_t done_;                                                \
                do {                                                           \
                    asm volatile(                                              \
                        "{\n\t.reg .pred P;\n\t"                              \
                        "mbarrier.try_wait.parity.acquire.cta.shared::cta.b64 P, [%1], %2, 0x989680;\n\t" \
                        "selp.b32 %0, 1, 0, P;\n\t}"                          \
                        : "=r"(done_) : "r"(mb_), "r"(PARVAR) : "memory");     \
                } while (!done_);                                              \
            }                                                                  \
            __syncwarp();                                                      \
            PARVAR ^= 1u;                                                      \
            if (tid == 0 && (T) + 2 < TS)                                      \
                asm volatile("mbarrier.arrive.expect_tx.shared.b64 _, [%0], %1;" :: "r"(mb_), "r"(1024u) : "memory"); \
        }                                                                      \
        /* hv loads: VOLATILE so they are re-issued every iteration */         \
        unsigned long long hv[16];                                             \
        asm volatile("ld.shared.v2.u64 {%0,%1}, [%2];" : "=l"(hv[0]),  "=l"(hv[1])  : "r"(HA[0])); \
        asm volatile("ld.shared.v2.u64 {%0,%1}, [%2];" : "=l"(hv[2]),  "=l"(hv[3])  : "r"(HA[1])); \
        asm volatile("ld.shared.v2.u64 {%0,%1}, [%2];" : "=l"(hv[4]),  "=l"(hv[5])  : "r"(HA[2])); \
        asm volatile("ld.shared.v2.u64 {%0,%1}, [%2];" : "=l"(hv[6]),  "=l"(hv[7])  : "r"(HA[3])); \
        asm volatile("ld.shared.v2.u64 {%0,%1}, [%2];" : "=l"(hv[8]),  "=l"(hv[9])  : "r"(HA[4])); \
        asm volatile("ld.shared.v2.u64 {%0,%1}, [%2];" : "=l"(hv[10]), "=l"(hv[11]) : "r"(HA[5])); \
        asm volatile("ld.shared.v2.u64 {%0,%1}, [%2];" : "=l"(hv[12]), "=l"(hv[13]) : "r"(HA[6])); \
        asm volatile("ld.shared.v2.u64 {%0,%1}, [%2];" : "=l"(hv[14]), "=l"(hv[15]) : "r"(HA[7])); \
        /* prefetch xg for t+2 (leaders only) */                               \
        float4 xg2_ = make_float4(0.f,0.f,0.f,0.f);                            \
        if (part == 0 && (T) + 2 < TS) {                                       \
            xg2_ = *(const float4*)xgp;                                        \
            xg2_.x *= 0.5f; xg2_.y *= 0.5f; xg2_.w *= 0.5f;                    \
        }                                                                      \
        unsigned long long a0 = (part == 0) ? (unsigned long long)__float_as_uint(xg_c.x) : 0ull; \
        unsigned long long a1 = (part == 0) ? (unsigned long long)__float_as_uint(xg_c.y) : 0ull; \
        unsigned long long a2 = (part == 0) ? (unsigned long long)__float_as_uint(xg_c.z) : 0ull; \
        unsigned long long a3 = (part == 0) ? (unsigned long long)__float_as_uint(xg_c.w) : 0ull; \
        _Pragma("unroll")                                                      \
        for (int j = 0; j < 16; j++) {                                         \
            asm("fma.rn.f32x2 %0, %1, %2, %0;" : "+l"(a0) : "l"(w[0][j]), "l"(hv[j])); \
            asm("fma.rn.f32x2 %0, %1, %2, %0;" : "+l"(a1) : "l"(w[1][j]), "l"(hv[j])); \
            asm("fma.rn.f32x2 %0, %1, %2, %0;" : "+l"(a2) : "l"(w[2][j]), "l"(hv[j])); \
            asm("fma.rn.f32x2 %0, %1, %2, %0;" : "+l"(a3) : "l"(w[3][j]), "l"(hv[j])); \
        }                                                                      \
        float s0, s1, s2, s3;                                                  \
        {                                                                      \
            uint32_t lo_, hi_;                                                 \
            asm("mov.b64 {%0,%1}, %2;" : "=r"(lo_), "=r"(hi_) : "l"(a0));      \
            s0 = __uint_as_float(lo_) + __uint_as_float(hi_);                  \
            asm("mov.b64 {%0,%1}, %2;" : "=r"(lo_), "=r"(hi_) : "l"(a1));      \
            s1 = __uint_as_float(lo_) + __uint_as_float(hi_);                  \
            asm("mov.b64 {%0,%1}, %2;" : "=r"(lo_), "=r"(hi_) : "l"(a2));      \
            s2 = __uint_as_float(lo_) + __uint_as_float(hi_);                  \
            asm("mov.b64 {%0,%1}, %2;" : "=r"(lo_), "=r"(hi_) : "l"(a3));      \
            s3 = __uint_as_float(lo_) + __uint_as_float(hi_);                  \
        }                                                                      \
        _Pragma("unroll")                                                      \
        for (int m = 4; m; m >>= 1) {                                          \
            s0 += __shfl_xor_sync(0xffffffffu, s0, m);                         \
            s1 += __shfl_xor_sync(0xffffffffu, s1, m);                         \
            s2 += __shfl_xor_sync(0xffffffffu, s2, m);                         \
            s3 += __shfl_xor_sync(0xffffffffu, s3, m);                         \
        }                                                                      \
        if (part == 0) {                                                       \
            float Ti = tanhapx(s0);                                            \
            float Tf = tanhapx(s1);                                            \
            float Tg = tanhapx(s2);                                            \
            float To = tanhapx(s3);                                            \
            float ii = 0.5f + 0.5f * Ti;                                       \
            float ff = 0.5f + 0.5f * Tf;                                       \
            float oo = 0.5f + 0.5f * To;                                       \
            c = ff * c + ii * Tg;                                              \
            float hnew = oo * tanhapx(c);                                      \
            if ((T) + 1 < TS) {                                                \
                const uint32_t hval = __float_as_uint(hnew);                   \
                const uint32_t doff = (BUFLIT) ? dof0 : dof1;  /* nbuf */      \
                const uint32_t moff = (BUFLIT) ? mof0 : mof1;                  \
                _Pragma("unroll")                                              \
                for (int k = 0; k < 8; k++) {                                  \
                    asm volatile(                                              \
                        "st.async.weak.shared::cluster.mbarrier::complete_tx::bytes.b32 [%0], %1, [%2];" \
                        :: "r"(r_hb[k] + doff), "r"(hval), "r"(r_hb[k] + moff) : "memory"); \
                }                                                              \
            }                                                                  \
            *hsp = hnew;                                                       \
            hsp += 256;                                                        \
            xgp += 1024;                                                       \
            xg_c = xg_n;                                                       \
            xg_n = xg2_;                                                       \
        }                                                                      \
    } while (0)

    // t = 0 (no wait; reads preloaded hb[0], sends into buf1)
    SCAN_STEP(0, 0, par0, ha0, false);
    // pairs t = 1..65534
    for (int t = 1; t < TS - 1; t += 2) {
        SCAN_STEP(t,     1, par1, ha1, true);
        SCAN_STEP(t + 1, 0, par0, ha0, true);
    }
    // tail t = 65535 (buf 1; no sends, no prefetch)
    SCAN_STEP(TS - 1, 1, par1, ha1, true);

#undef SCAN_STEP
}

// ---------------------------------------------------------------------------
// GEMM 2 + epilogue: out[t][r] = 2*sigmoid( sum_k hs[t][k]*fc_W[r][k] + fc_b[r] )
// ---------------------------------------------------------------------------
__global__ __launch_bounds__(256) void fc_kernel(
    const float* __restrict__ Wf,   // [256,256]
    const float* __restrict__ bf,
    float* __restrict__ out)
{
    __shared__ float Xs[32][65];
    __shared__ float Ws[32][65];
    const int lin = threadIdx.x;
    const int tx = lin & 15, ty = lin >> 4;
    const int bt = blockIdx.x * 64;
    const int br = blockIdx.y * 64;
    float acc[4][4] = {};

    for (int k0 = 0; k0 < 256; k0 += 32) {
        int row = lin >> 3, seg = (lin & 7) << 2;
        float4 v = *(const float4*)&g_hs[(size_t)(bt + row) * 256 + k0 + seg];
        Xs[seg+0][row] = v.x; Xs[seg+1][row] = v.y; Xs[seg+2][row] = v.z; Xs[seg+3][row] = v.w;
        float4 v2 = *(const float4*)&g_hs[(size_t)(bt + row + 32) * 256 + k0 + seg];
        Xs[seg+0][row+32] = v2.x; Xs[seg+1][row+32] = v2.y; Xs[seg+2][row+32] = v2.z; Xs[seg+3][row+32] = v2.w;
        float4 w1 = *(const float4*)&Wf[(size_t)(br + row) * 256 + k0 + seg];
        Ws[seg+0][row] = w1.x; Ws[seg+1][row] = w1.y; Ws[seg+2][row] = w1.z; Ws[seg+3][row] = w1.w;
        float4 w2 = *(const float4*)&Wf[(size_t)(br + row + 32) * 256 + k0 + seg];
        Ws[seg+0][row+32] = w2.x; Ws[seg+1][row+32] = w2.y; Ws[seg+2][row+32] = w2.z; Ws[seg+3][row+32] = w2.w;
        __syncthreads();
#pragma unroll
        for (int kk = 0; kk < 32; kk++) {
            float a[4], bb[4];
#pragma unroll
            for (int i = 0; i < 4; i++) a[i] = Xs[kk][ty*4 + i];
#pragma unroll
            for (int j = 0; j < 4; j++) bb[j] = Ws[kk][tx*4 + j];
#pragma unroll
            for (int i = 0; i < 4; i++)
#pragma unroll
                for (int j = 0; j < 4; j++) acc[i][j] = fmaf(a[i], bb[j], acc[i][j]);
        }
        __syncthreads();
    }
#pragma unroll
    for (int j = 0; j < 4; j++) {
        int r = br + tx*4 + j;
        float bias = bf[r];
#pragma unroll
        for (int i = 0; i < 4; i++) {
            int t = bt + ty*4 + i;
            out[(size_t)t * 256 + r] = 2.0f * fsig(acc[i][j] + bias);
        }
    }
}

// ---------------------------------------------------------------------------
extern "C" void kernel_launch(void* const* d_in, const int* in_sizes, int n_in,
                              void* d_out, int out_size)
{
    (void)in_sizes; (void)n_in; (void)out_size;
    const float* x      = (const float*)d_in[0];
    const float* W_ih2  = (const float*)d_in[7];
    const float* W_hh2  = (const float*)d_in[8];
    const float* b_ih2  = (const float*)d_in[9];
    const float* b_hh2  = (const float*)d_in[10];
    const float* h0_2   = (const float*)d_in[11];
    const float* c0_2   = (const float*)d_in[12];
    const float* fc_W   = (const float*)d_in[13];
    const float* fc_b   = (const float*)d_in[14];
    float* out = (float*)d_out;

    gemm_xg_kernel<<<dim3(TS / 64, 16), 256>>>(x, W_ih2, b_ih2, b_hh2);
    scan_kernel<<<8, 256>>>(W_hh2, h0_2, c0_2);
    fc_kernel<<<dim3(TS / 64, 4), 256>>>(fc_W, fc_b, out);
}